// round 1
// baseline (speedup 1.0000x reference)
#include <cuda_runtime.h>

// Problem constants
#define BATCH 2
#define DD 160
#define HH 160
#define WW 160
#define PLANE (HH * WW)               // 25600
#define NVOX (BATCH * DD * HH * WW)   // 8,192,000
#define NCH 5
#define RAD 4
#define INV_WIN (1.0f / 729.0f)

// D-pass chunking
#define CDCHUNK 32
#define NCHUNK (DD / CDCHUNK)         // 5
#define NBLK3 (NCHUNK * BATCH * HH)   // 1600

// Scratch (allocation-free: __device__ globals)
__device__ float g_bufA[(size_t)NCH * NVOX];   // after W pass
__device__ float g_bufB[(size_t)NCH * NVOX];   // after H pass
__device__ float g_partial[NBLK3];

// ---------------------------------------------------------------------------
// Pass 1: compute the 5 per-voxel products and sliding-sum along W (contiguous)
// grid = B*D*H rows, block = 160 threads (one per w)
// ---------------------------------------------------------------------------
__global__ void __launch_bounds__(WW) pass_w_kernel(const float* __restrict__ I,
                                                    const float* __restrict__ J) {
    __shared__ float s[NCH][WW];
    const int w = threadIdx.x;
    const size_t base = (size_t)blockIdx.x * WW;   // blockIdx = (b*D + d)*H + h

    const float iv = I[base + w];
    const float jv = J[base + w];
    s[0][w] = iv;
    s[1][w] = jv;
    s[2][w] = iv * iv;
    s[3][w] = jv * jv;
    s[4][w] = iv * jv;
    __syncthreads();

    const int lo = max(w - RAD, 0);
    const int hi = min(w + RAD, WW - 1);
    float acc0 = 0.f, acc1 = 0.f, acc2 = 0.f, acc3 = 0.f, acc4 = 0.f;
    for (int x = lo; x <= hi; x++) {
        acc0 += s[0][x];
        acc1 += s[1][x];
        acc2 += s[2][x];
        acc3 += s[3][x];
        acc4 += s[4][x];
    }
    g_bufA[0 * (size_t)NVOX + base + w] = acc0;
    g_bufA[1 * (size_t)NVOX + base + w] = acc1;
    g_bufA[2 * (size_t)NVOX + base + w] = acc2;
    g_bufA[3 * (size_t)NVOX + base + w] = acc3;
    g_bufA[4 * (size_t)NVOX + base + w] = acc4;
}

// ---------------------------------------------------------------------------
// Pass 2: sliding-sum along H (stride W) with a running window.
// grid = NCH*B*D blocks; block = 160 threads (one per w); each thread walks h.
// ---------------------------------------------------------------------------
__global__ void __launch_bounds__(WW) pass_h_kernel() {
    const int w = threadIdx.x;
    const int cbd = blockIdx.x;               // c*(B*D) + b*D + d
    const size_t base = (size_t)cbd * PLANE + w;   // contiguous per (c,b,d) slab

    const float* __restrict__ in = g_bufA;
    float* __restrict__ out = g_bufB;

    float s = 0.f;
    #pragma unroll
    for (int h = 0; h <= RAD; h++) s += in[base + (size_t)h * WW];
    out[base] = s;

    // ramp-up region: h in [1, RAD]  (only adds)
    #pragma unroll
    for (int h = 1; h <= RAD; h++) {
        s += in[base + (size_t)(h + RAD) * WW];
        out[base + (size_t)h * WW] = s;
    }
    // steady region: h in [RAD+1, H-RAD-1]  (add + sub, unconditional)
    #pragma unroll 4
    for (int h = RAD + 1; h < HH - RAD; h++) {
        s += in[base + (size_t)(h + RAD) * WW];
        s -= in[base + (size_t)(h - RAD - 1) * WW];
        out[base + (size_t)h * WW] = s;
    }
    // ramp-down region: h in [H-RAD, H-1]  (only subs)
    #pragma unroll
    for (int h = HH - RAD; h < HH; h++) {
        s -= in[base + (size_t)(h - RAD - 1) * WW];
        out[base + (size_t)h * WW] = s;
    }
}

// ---------------------------------------------------------------------------
// Pass 3: sliding-sum along D (stride H*W) for all 5 channels + fused NCC
// computation + deterministic block reduction of the cc sum.
// grid = NCHUNK*B*H blocks; block = 160 threads (one per w).
// ---------------------------------------------------------------------------
__global__ void __launch_bounds__(WW) pass_d_kernel() {
    const int w = threadIdx.x;
    int bi = blockIdx.x;                      // chunk*(B*H) + b*H + h
    const int chunk = bi / (BATCH * HH);
    const int bh = bi % (BATCH * HH);
    const int b = bh / HH;
    const int h = bh % HH;
    const int d0 = chunk * CDCHUNK;

    // address of (b, d, h, w) = b*D*PLANE + d*PLANE + h*W + w
    const size_t base = (size_t)b * DD * PLANE + (size_t)h * WW + w;
    const float* __restrict__ in = g_bufB;

    // init running windows for output d0 (covers input d in [d0-4, d0+4])
    float s[NCH];
    #pragma unroll
    for (int c = 0; c < NCH; c++) {
        float a = 0.f;
        #pragma unroll
        for (int dd = d0 - RAD; dd <= d0 + RAD; dd++) {
            if (dd >= 0 && dd < DD)
                a += in[(size_t)c * NVOX + base + (size_t)dd * PLANE];
        }
        s[c] = a;
    }

    float cc_sum = 0.f;
    for (int d = d0; d < d0 + CDCHUNK; d++) {
        const float Is = s[0], Js = s[1], I2 = s[2], J2 = s[3], IJ = s[4];
        const float cross = IJ - Is * Js * INV_WIN;
        const float Iv = I2 - Is * Is * INV_WIN;
        const float Jv = J2 - Js * Js * INV_WIN;
        const float cc = (cross * cross) / (Iv * Jv + 1e-5f);
        cc_sum += cc;

        if (d != d0 + CDCHUNK - 1) {
            const int add = d + 1 + RAD;
            const int rem = d - RAD;
            #pragma unroll
            for (int c = 0; c < NCH; c++) {
                if (add < DD) s[c] += in[(size_t)c * NVOX + base + (size_t)add * PLANE];
                if (rem >= 0) s[c] -= in[(size_t)c * NVOX + base + (size_t)rem * PLANE];
            }
        }
    }

    // deterministic reduction: warp shuffle (fixed order), then 5 warp sums
    #pragma unroll
    for (int off = 16; off > 0; off >>= 1)
        cc_sum += __shfl_down_sync(0xFFFFFFFFu, cc_sum, off);

    __shared__ float warp_sums[WW / 32];
    const int lane = w & 31, warp = w >> 5;
    if (lane == 0) warp_sums[warp] = cc_sum;
    __syncthreads();
    if (w == 0) {
        float t = 0.f;
        #pragma unroll
        for (int i = 0; i < WW / 32; i++) t += warp_sums[i];
        g_partial[blockIdx.x] = t;
    }
}

// ---------------------------------------------------------------------------
// Pass 4: final deterministic reduction of 1600 block partials -> scalar out
// ---------------------------------------------------------------------------
__global__ void finalize_kernel(float* __restrict__ out) {
    __shared__ float red[256];
    float a = 0.f;
    for (int i = threadIdx.x; i < NBLK3; i += 256) a += g_partial[i];
    red[threadIdx.x] = a;
    __syncthreads();
    #pragma unroll
    for (int off = 128; off > 0; off >>= 1) {
        if (threadIdx.x < off) red[threadIdx.x] += red[threadIdx.x + off];
        __syncthreads();
    }
    if (threadIdx.x == 0) out[0] = -red[0] / (float)NVOX;
}

// ---------------------------------------------------------------------------
extern "C" void kernel_launch(void* const* d_in, const int* in_sizes, int n_in,
                              void* d_out, int out_size) {
    const float* y_true = (const float*)d_in[0];
    const float* y_pred = (const float*)d_in[1];
    float* out = (float*)d_out;

    pass_w_kernel<<<BATCH * DD * HH, WW>>>(y_true, y_pred);
    pass_h_kernel<<<NCH * BATCH * DD, WW>>>();
    pass_d_kernel<<<NBLK3, WW>>>();
    finalize_kernel<<<1, 256>>>(out);
}